// round 10
// baseline (speedup 1.0000x reference)
#include <cuda_runtime.h>
#include <cuda_bf16.h>
#include <math.h>
#include <cstdint>

// Problem constants
#define BATCH 2
#define SEQ   2048
#define EMB   1024
#define NH    16
#define NKV   4
#define HD    64
#define KVDIM 256
#define ROWS  (BATCH*SEQ)     // 4096
#define K2    2048            // [Ah | Al] x [Bh | Bl]; compute hh + hl + lh
#define QKVW  (EMB + 2*KVDIM) // 1536

// flash tiling: QT=128 rows per CTA, 4 warps x 32 rows, KT=64 keys
#define QT 128
#define KT 64
#define QS_STR 136
#define VS_STR 72

#define QSCALE (0.125f * 1.44269504089f)

// flash smem layout (bytes)
#define SM_Q   0
#define SM_K   34816
#define SM_VH  (SM_K + 17408)
#define SM_VL  (SM_VH + 9216)
#define SM_TOT (SM_VL + 9216)              // 70656

// fused conversion grid partition
#define NBLK_A  (ROWS * EMB / 256)         // 16384
#define NBLK_WQ 1024                       // (1024/32)*(1024/32)
#define NBLK_WK 256
#define NBLK_WV 256
#define NBLK_WO 1024
#define NBLK_CONV (NBLK_A + NBLK_WQ + NBLK_WK + NBLK_WV + NBLK_WO)

// ---------------- scratch ----------------
__device__ __nv_bfloat16 g_QKVh[ROWS * QKVW];
__device__ __nv_bfloat16 g_QKVl[ROWS * QKVW];
__device__ __nv_bfloat16 g_A   [ROWS * K2];
__device__ __nv_bfloat16 g_Bqkv[QKVW * K2];
__device__ __nv_bfloat16 g_Bo  [EMB  * K2];

// ---------------- helpers ----------------
__device__ __forceinline__ uint32_t smem_u32(const void* p) {
    uint32_t a;
    asm("{ .reg .u64 t; cvta.to.shared.u64 t, %1; cvt.u32.u64 %0, t; }" : "=r"(a) : "l"(p));
    return a;
}
__device__ __forceinline__ void ldsm_x4(uint32_t* r, uint32_t addr) {
    asm volatile("ldmatrix.sync.aligned.m8n8.x4.shared.b16 {%0,%1,%2,%3}, [%4];"
        : "=r"(r[0]), "=r"(r[1]), "=r"(r[2]), "=r"(r[3]) : "r"(addr));
}
__device__ __forceinline__ void ldsm_x2(uint32_t* r, uint32_t addr) {
    asm volatile("ldmatrix.sync.aligned.m8n8.x2.shared.b16 {%0,%1}, [%2];"
        : "=r"(r[0]), "=r"(r[1]) : "r"(addr));
}
__device__ __forceinline__ void ldsm_x2t(uint32_t* r, uint32_t addr) {
    asm volatile("ldmatrix.sync.aligned.m8n8.x2.trans.shared.b16 {%0,%1}, [%2];"
        : "=r"(r[0]), "=r"(r[1]) : "r"(addr));
}
__device__ __forceinline__ void mma16816(float* c, const uint32_t* a, const uint32_t* b) {
    asm volatile("mma.sync.aligned.m16n8k16.row.col.f32.bf16.bf16.f32 "
        "{%0,%1,%2,%3}, {%4,%5,%6,%7}, {%8,%9}, {%0,%1,%2,%3};"
        : "+f"(c[0]), "+f"(c[1]), "+f"(c[2]), "+f"(c[3])
        : "r"(a[0]), "r"(a[1]), "r"(a[2]), "r"(a[3]), "r"(b[0]), "r"(b[1]));
}
__device__ __forceinline__ float ex2f(float x) {
    float y;
    asm("ex2.approx.ftz.f32 %0, %1;" : "=f"(y) : "f"(x));
    return y;
}
__device__ __forceinline__ uint32_t pack_bf2(float a, float b) {
    __nv_bfloat162 t = __floats2bfloat162_rn(a, b);
    return *(uint32_t*)&t;
}
__device__ __forceinline__ uint32_t sw64(uint32_t off) {
    return off ^ ((off >> 3) & 0x30);
}
#define CP_ASYNC16(dst, src) \
    asm volatile("cp.async.cg.shared.global [%0], [%1], 16;" :: "r"(dst), "l"(src))
#define CP_COMMIT() asm volatile("cp.async.commit_group;" ::: "memory")
#define CP_WAIT1()  asm volatile("cp.async.wait_group 1;" ::: "memory")
#define CP_WAIT0()  asm volatile("cp.async.wait_group 0;" ::: "memory")

// ---------------- fused split-precision conversions (one launch) ----------------
// blocks [0, NBLK_A): X [4096,1024] fp32 -> A [4096, 2048] = [hi | lo]
// blocks [NBLK_A, ...): tiled transpose W [1024,N] -> Bt [N,2048] = [hi | lo]
__global__ __launch_bounds__(256) void conv_fused(
    const float* __restrict__ X,
    const float* __restrict__ Wq, const float* __restrict__ Wk,
    const float* __restrict__ Wv, const float* __restrict__ Wo,
    __nv_bfloat16* __restrict__ A,
    __nv_bfloat16* __restrict__ Bqkv, __nv_bfloat16* __restrict__ Bo)
{
    __shared__ float t[32][33];
    int bid = blockIdx.x;
    const int tid = threadIdx.x;

    if (bid < NBLK_A) {
        int idx = bid * 256 + tid;
        int r = idx >> 10, c = idx & 1023;
        float v = X[idx];
        __nv_bfloat16 h = __float2bfloat16(v);
        __nv_bfloat16 l = __float2bfloat16(v - __bfloat162float(h));
        size_t base = (size_t)r * K2;
        A[base + c] = h;
        A[base + 1024 + c] = l;
        return;
    }
    bid -= NBLK_A;

    const float* W;
    __nv_bfloat16* dst;
    int N, nx;
    if (bid < NBLK_WQ)                     { W = Wq; dst = Bqkv;                               N = EMB;   nx = 32; }
    else if (bid < NBLK_WQ + NBLK_WK)      { W = Wk; dst = Bqkv + (size_t)EMB * K2;            N = KVDIM; nx = 8;  bid -= NBLK_WQ; }
    else if (bid < NBLK_WQ + 2 * NBLK_WK)  { W = Wv; dst = Bqkv + (size_t)(EMB + KVDIM) * K2;  N = KVDIM; nx = 8;  bid -= NBLK_WQ + NBLK_WK; }
    else                                   { W = Wo; dst = Bo;                                 N = EMB;   nx = 32; bid -= NBLK_WQ + 2 * NBLK_WK; }

    const int n0 = (bid % nx) * 32, k0 = (bid / nx) * 32;
    const int tx = tid & 31, ty = tid >> 5;    // 32 x 8
#pragma unroll
    for (int i = ty; i < 32; i += 8)
        t[i][tx] = W[(size_t)(k0 + i) * N + n0 + tx];
    __syncthreads();
#pragma unroll
    for (int i = ty; i < 32; i += 8) {
        float v = t[tx][i];
        __nv_bfloat16 h = __float2bfloat16(v);
        __nv_bfloat16 l = __float2bfloat16(v - __bfloat162float(h));
        size_t base = (size_t)(n0 + i) * K2 + k0 + tx;
        dst[base]        = h;
        dst[base + 1024] = l;
    }
}

// ---------------- pipelined HMMA split GEMM: C = Ah.Bh^T + Ah.Bl^T + Al.Bh^T ----------------
__global__ __launch_bounds__(256, 2) void gemm_bf16(
    const __nv_bfloat16* __restrict__ A,
    const __nv_bfloat16* __restrict__ Bt,
    float* __restrict__ C,
    __nv_bfloat16* __restrict__ Ch,
    __nv_bfloat16* __restrict__ Cl,
    int N, int mode)
{
    extern __shared__ __align__(128) char smem_g[];   // 2 stages x 32KB

    const int tid  = threadIdx.x;
    const int lane = tid & 31, wid = tid >> 5;
    const int wm = wid & 1;
    const int wn = wid >> 1;
    const int bx = blockIdx.x, by = blockIdx.y;

    const __nv_bfloat16* Ab = A  + (size_t)by * 128 * K2;
    const __nv_bfloat16* Bb = Bt + (size_t)bx * 128 * K2;

    float acc[4][4][4];
#pragma unroll
    for (int i = 0; i < 4; i++)
#pragma unroll
        for (int j = 0; j < 4; j++)
#pragma unroll
            for (int q = 0; q < 4; q++) acc[i][j][q] = 0.0f;

    const int a_r = wm * 64 + (lane & 15);
    const int a_c = (lane >> 4);
    const int b_r = wn * 32 + (lane & 7);
    const int b_c = ((lane >> 3) & 1);

    const int row_ld = tid >> 2, c16_ld = tid & 3;

    auto issue = [&](int ch, int s) {
        const int k0 = ch * 32;
        char* st = smem_g + s * 32768;
#pragma unroll
        for (int p = 0; p < 2; p++) {
            int row = row_ld + p * 64;
            uint32_t sw = sw64(row * 64 + c16_ld * 16);
            uint32_t d = smem_u32(st + sw);
            const __nv_bfloat16* ga = Ab + (size_t)row * K2 + k0 + c16_ld * 8;
            const __nv_bfloat16* gb = Bb + (size_t)row * K2 + k0 + c16_ld * 8;
            CP_ASYNC16(d,         (const char*)ga);
            CP_ASYNC16(d + 8192,  (const char*)(ga + 1024));
            CP_ASYNC16(d + 16384, (const char*)gb);
            CP_ASYNC16(d + 24576, (const char*)(gb + 1024));
        }
        CP_COMMIT();
    };

    const int NCH = 1024 / 32;
    issue(0, 0);

    for (int ch = 0; ch < NCH; ch++) {
        const int s = ch & 1;
        if (ch + 1 < NCH) { issue(ch + 1, (ch + 1) & 1); CP_WAIT1(); }
        else              { CP_WAIT0(); }
        __syncthreads();

        const uint32_t su = smem_u32(smem_g + s * 32768);
#pragma unroll
        for (int ks = 0; ks < 2; ks++) {
            uint32_t bh[4][2], bl[4][2];
#pragma unroll
            for (int j = 0; j < 4; j++) {
                int row = b_r + j * 8;
                uint32_t off = sw64(row * 64 + (b_c + ks * 2) * 16);
                ldsm_x2(bh[j], su + 16384 + off);
                ldsm_x2(bl[j], su + 24576 + off);
            }
#pragma unroll
            for (int i = 0; i < 4; i++) {
                int row = a_r + i * 16;
                uint32_t off = sw64(row * 64 + (a_c + ks * 2) * 16);
                uint32_t ah[4], al[4];
                ldsm_x4(ah, su + off);
                ldsm_x4(al, su + 8192 + off);
#pragma unroll
                for (int j = 0; j < 4; j++) {
                    mma16816(acc[i][j], ah, bh[j]);
                    mma16816(acc[i][j], ah, bl[j]);
                    mma16816(acc[i][j], al, bh[j]);
                }
            }
        }
        __syncthreads();
    }

#pragma unroll
    for (int i = 0; i < 4; i++)
#pragma unroll
        for (int j = 0; j < 4; j++) {
            int r0  = by * 128 + wm * 64 + i * 16 + (lane >> 2);
            int col = bx * 128 + wn * 32 + j * 8 + (lane & 3) * 2;
            if (mode == 0) {
                float* p0 = C + (size_t)r0 * N + col;
                p0[0] = acc[i][j][0]; p0[1] = acc[i][j][1];
                float* p1 = p0 + (size_t)8 * N;
                p1[0] = acc[i][j][2]; p1[1] = acc[i][j][3];
            } else {
                float sc = (col < EMB) ? QSCALE : 1.0f;
                float v0 = acc[i][j][0] * sc, v1 = acc[i][j][1] * sc;
                float v2 = acc[i][j][2] * sc, v3 = acc[i][j][3] * sc;
                __nv_bfloat162 h01 = __floats2bfloat162_rn(v0, v1);
                __nv_bfloat162 h23 = __floats2bfloat162_rn(v2, v3);
                *(uint32_t*)(Ch + (size_t)r0 * N + col)       = *(uint32_t*)&h01;
                *(uint32_t*)(Ch + (size_t)(r0 + 8) * N + col) = *(uint32_t*)&h23;
                *(uint32_t*)(Cl + (size_t)r0 * N + col) =
                    pack_bf2(v0 - __bfloat162float(h01.x), v1 - __bfloat162float(h01.y));
                *(uint32_t*)(Cl + (size_t)(r0 + 8) * N + col) =
                    pack_bf2(v2 - __bfloat162float(h23.x), v3 - __bfloat162float(h23.y));
            }
        }
}

// ---------------- HMMA flash attention: heavy-first (LPT) scheduling ----------------
// grid (NH, BATCH, SEQ/QT) with qb = gridDim.z-1-blockIdx.z so heaviest CTAs launch first.
__global__ __launch_bounds__(128) void flash_hmma(
    const __nv_bfloat16* __restrict__ QKVh,
    const __nv_bfloat16* __restrict__ QKVl,
    __nv_bfloat16* __restrict__ Aout)
{
    extern __shared__ __align__(16) char smem[];
    __nv_bfloat16* Qs = (__nv_bfloat16*)(smem + SM_Q);
    __nv_bfloat16* Ks = (__nv_bfloat16*)(smem + SM_K);
    __nv_bfloat16* Vh = (__nv_bfloat16*)(smem + SM_VH);
    __nv_bfloat16* Vl = (__nv_bfloat16*)(smem + SM_VL);

    const int h = blockIdx.x, b = blockIdx.y;
    const int qb = (int)gridDim.z - 1 - (int)blockIdx.z;   // heavy first
    const int g = h >> 2;
    const int tid = threadIdx.x, lane = tid & 31, wid = tid >> 5;

    const int row_ld = (tid >> 4);
    const int c4  = tid & 15;
    const int hi  = (c4 < 8);
    const __nv_bfloat16* src_ld = (hi ? QKVh : QKVl);
    const int co = (hi ? c4 : c4 - 8) * 8;
    const int kdst = (hi ? co : 64 + co);

#pragma unroll
    for (int it = 0; it < 16; it++) {
        int r = it * 8 + row_ld;
        *(uint4*)(Qs + r * QS_STR + kdst) =
            *(const uint4*)(src_ld + (size_t)(b * SEQ + qb * QT + r) * QKVW + h * HD + co);
    }
    __syncthreads();

    const uint32_t sQ = smem_u32(Qs);
    const uint32_t aQ0 = sQ + ((wid * 32 + (lane & 15)) * QS_STR + ((lane >> 4) << 3)) * 2;
    const uint32_t aQ1 = aQ0 + 16 * QS_STR * 2;
    uint32_t qh[2][4][4];
#pragma unroll
    for (int c = 0; c < 4; c++) {
        ldsm_x4(qh[0][c], aQ0 + (c * 16) * 2);
        ldsm_x4(qh[1][c], aQ1 + (c * 16) * 2);
    }

    float accO[2][8][4];
#pragma unroll
    for (int t = 0; t < 2; t++)
#pragma unroll
        for (int n = 0; n < 8; n++)
#pragma unroll
            for (int q = 0; q < 4; q++) accO[t][n][q] = 0.0f;
    float mrow[2][2], lrow[2][2];
#pragma unroll
    for (int t = 0; t < 2; t++) { mrow[t][0] = mrow[t][1] = -INFINITY; lrow[t][0] = lrow[t][1] = 0.0f; }

    const uint32_t bKh = smem_u32(Ks) + (((lane & 7)) * QS_STR + (((lane >> 3) & 1) << 3)) * 2;
    const uint32_t sVh = smem_u32(Vh), sVl = smem_u32(Vl);
    const uint32_t bVrow = (lane & 15) * VS_STR * 2;

    const int ktmax = 2 * qb + 1;
    for (int kt = 0; kt <= ktmax; kt++) {
#pragma unroll
        for (int it = 0; it < 8; it++) {
            int r = it * 8 + row_ld;
            size_t base = (size_t)(b * SEQ + kt * KT + r) * QKVW + EMB + g * HD;
            *(uint4*)(Ks + r * QS_STR + kdst) = *(const uint4*)(src_ld + base + co);
            *(uint4*)((hi ? Vh : Vl) + r * VS_STR + co) = *(const uint4*)(src_ld + base + KVDIM + co);
        }
        __syncthreads();

        float s[2][8][4];
#pragma unroll
        for (int t = 0; t < 2; t++)
#pragma unroll
            for (int n = 0; n < 8; n++)
#pragma unroll
                for (int q = 0; q < 4; q++) s[t][n][q] = 0.0f;

#pragma unroll
        for (int c = 0; c < 4; c++) {
            uint32_t ql0[4], ql1[4];
            ldsm_x4(ql0, aQ0 + (64 + c * 16) * 2);
            ldsm_x4(ql1, aQ1 + (64 + c * 16) * 2);
#pragma unroll
            for (int n = 0; n < 8; n++) {
                uint32_t kh2[2], kl2[2];
                ldsm_x2(kh2, bKh + (n * 8 * QS_STR + c * 16) * 2);
                mma16816(s[0][n], qh[0][c], kh2);
                mma16816(s[0][n], ql0, kh2);
                mma16816(s[1][n], qh[1][c], kh2);
                mma16816(s[1][n], ql1, kh2);
                ldsm_x2(kl2, bKh + (n * 8 * QS_STR + 64 + c * 16) * 2);
                mma16816(s[0][n], qh[0][c], kl2);
                mma16816(s[1][n], qh[1][c], kl2);
            }
        }

        if (kt >= 2 * qb) {
#pragma unroll
            for (int t = 0; t < 2; t++) {
                int rbase = qb * QT + wid * 32 + t * 16 + (lane >> 2);
#pragma unroll
                for (int n = 0; n < 8; n++) {
#pragma unroll
                    for (int q = 0; q < 4; q++) {
                        int colg = kt * KT + n * 8 + (lane & 3) * 2 + (q & 1);
                        int rowg = rbase + ((q >= 2) ? 8 : 0);
                        if (colg > rowg) s[t][n][q] = -1e30f;
                    }
                }
            }
        }

#pragma unroll
        for (int t = 0; t < 2; t++) {
            float mx0 = -INFINITY, mx1 = -INFINITY;
#pragma unroll
            for (int n = 0; n < 8; n++) {
                mx0 = fmaxf(mx0, fmaxf(s[t][n][0], s[t][n][1]));
                mx1 = fmaxf(mx1, fmaxf(s[t][n][2], s[t][n][3]));
            }
            mx0 = fmaxf(mx0, __shfl_xor_sync(0xffffffffu, mx0, 1));
            mx0 = fmaxf(mx0, __shfl_xor_sync(0xffffffffu, mx0, 2));
            mx1 = fmaxf(mx1, __shfl_xor_sync(0xffffffffu, mx1, 1));
            mx1 = fmaxf(mx1, __shfl_xor_sync(0xffffffffu, mx1, 2));
            float mn0 = fmaxf(mrow[t][0], mx0), mn1 = fmaxf(mrow[t][1], mx1);
            float s0 = ex2f(mrow[t][0] - mn0), s1 = ex2f(mrow[t][1] - mn1);
            lrow[t][0] *= s0; lrow[t][1] *= s1;
#pragma unroll
            for (int n = 0; n < 8; n++) {
                accO[t][n][0] *= s0; accO[t][n][1] *= s0;
                accO[t][n][2] *= s1; accO[t][n][3] *= s1;
            }
            mrow[t][0] = mn0; mrow[t][1] = mn1;

            uint32_t phx[8], phy[8], plx[8], ply[8];
#pragma unroll
            for (int n = 0; n < 8; n++) {
                float p0 = ex2f(s[t][n][0] - mn0);
                float p1 = ex2f(s[t][n][1] - mn0);
                float p2 = ex2f(s[t][n][2] - mn1);
                float p3 = ex2f(s[t][n][3] - mn1);
                lrow[t][0] += p0 + p1; lrow[t][1] += p2 + p3;
                __nv_bfloat162 h01 = __floats2bfloat162_rn(p0, p1);
                __nv_bfloat162 h23 = __floats2bfloat162_rn(p2, p3);
                phx[n] = *(uint32_t*)&h01;
                phy[n] = *(uint32_t*)&h23;
                plx[n] = pack_bf2(p0 - __bfloat162float(h01.x), p1 - __bfloat162float(h01.y));
                ply[n] = pack_bf2(p2 - __bfloat162float(h23.x), p3 - __bfloat162float(h23.y));
            }

#pragma unroll
            for (int kc = 0; kc < 4; kc++) {
                uint32_t aH[4] = {phx[2 * kc], phy[2 * kc], phx[2 * kc + 1], phy[2 * kc + 1]};
                uint32_t aL[4] = {plx[2 * kc], ply[2 * kc], plx[2 * kc + 1], ply[2 * kc + 1]};
#pragma unroll
                for (int n = 0; n < 8; n++) {
                    uint32_t bh2[2], bl2[2];
                    ldsm_x2t(bh2, sVh + (kc * 16 * VS_STR + n * 8) * 2 + bVrow);
                    ldsm_x2t(bl2, sVl + (kc * 16 * VS_STR + n * 8) * 2 + bVrow);
                    mma16816(accO[t][n], aH, bh2);
                    mma16816(accO[t][n], aL, bh2);
                    mma16816(accO[t][n], aH, bl2);
                }
            }
        }
        __syncthreads();
    }

    // ---- finalize: normalize + split store into A layout [hi|lo] ----
#pragma unroll
    for (int t = 0; t < 2; t++) {
        float l0 = lrow[t][0], l1 = lrow[t][1];
        l0 += __shfl_xor_sync(0xffffffffu, l0, 1);
        l0 += __shfl_xor_sync(0xffffffffu, l0, 2);
        l1 += __shfl_xor_sync(0xffffffffu, l1, 1);
        l1 += __shfl_xor_sync(0xffffffffu, l1, 2);
        const float inv0 = 1.0f / l0, inv1 = 1.0f / l1;

        const int r0 = qb * QT + wid * 32 + t * 16 + (lane >> 2);
#pragma unroll
        for (int n = 0; n < 8; n++) {
            int col = h * HD + n * 8 + (lane & 3) * 2;
            float v0 = accO[t][n][0] * inv0, v1 = accO[t][n][1] * inv0;
            float v2 = accO[t][n][2] * inv1, v3 = accO[t][n][3] * inv1;
            __nv_bfloat162 h01 = __floats2bfloat162_rn(v0, v1);
            __nv_bfloat162 h23 = __floats2bfloat162_rn(v2, v3);
            uint32_t lo01 = pack_bf2(v0 - __bfloat162float(h01.x), v1 - __bfloat162float(h01.y));
            uint32_t lo23 = pack_bf2(v2 - __bfloat162float(h23.x), v3 - __bfloat162float(h23.y));
            size_t ra = (size_t)(b * SEQ + r0) * K2;
            size_t rb = (size_t)(b * SEQ + r0 + 8) * K2;
            *(uint32_t*)(Aout + ra + col)        = *(uint32_t*)&h01;
            *(uint32_t*)(Aout + ra + 1024 + col) = lo01;
            *(uint32_t*)(Aout + rb + col)        = *(uint32_t*)&h23;
            *(uint32_t*)(Aout + rb + 1024 + col) = lo23;
        }
    }
}

// ---------------- launch ----------------
extern "C" void kernel_launch(void* const* d_in, const int* in_sizes, int n_in,
                              void* d_out, int out_size)
{
    const float* x  = (const float*)d_in[0];
    const float* Wq = (const float*)d_in[1];
    const float* Wk = (const float*)d_in[2];
    const float* Wv = (const float*)d_in[3];
    const float* Wo = (const float*)d_in[4];
    float* out = (float*)d_out;

    __nv_bfloat16 *QKVh, *QKVl, *A, *Bqkv, *Bo;
    cudaGetSymbolAddress((void**)&QKVh, g_QKVh);
    cudaGetSymbolAddress((void**)&QKVl, g_QKVl);
    cudaGetSymbolAddress((void**)&A, g_A);
    cudaGetSymbolAddress((void**)&Bqkv, g_Bqkv);
    cudaGetSymbolAddress((void**)&Bo, g_Bo);

    static bool attr_set = false;
    if (!attr_set) {
        cudaFuncSetAttribute(flash_hmma, cudaFuncAttributeMaxDynamicSharedMemorySize, SM_TOT);
        cudaFuncSetAttribute(gemm_bf16, cudaFuncAttributeMaxDynamicSharedMemorySize, 65536);
        attr_set = true;
    }

    // fused split-precision conversions (one launch)
    conv_fused<<<NBLK_CONV, 256>>>(x, Wq, Wk, Wv, Wo, A, Bqkv, Bo);

    // fused QKV projection -> split bf16 (Q pre-scaled)
    gemm_bf16<<<dim3(QKVW / 128, ROWS / 128), 256, 65536>>>(
        A, Bqkv, nullptr, QKVh, QKVl, QKVW, 1);

    // flash attention (heavy-first) -> split A layout
    flash_hmma<<<dim3(NH, BATCH, SEQ / QT), 128, SM_TOT>>>(QKVh, QKVl, A);

    // output projection -> fp32 out
    gemm_bf16<<<dim3(EMB / 128, ROWS / 128), 256, 65536>>>(
        A, Bo, out, nullptr, nullptr, EMB, 0);
}

// round 11
// speedup vs baseline: 1.2440x; 1.2440x over previous
#include <cuda_runtime.h>
#include <cuda_bf16.h>
#include <math.h>
#include <cstdint>

// Problem constants
#define BATCH 2
#define SEQ   2048
#define EMB   1024
#define NH    16
#define NKV   4
#define HD    64
#define KVDIM 256
#define ROWS  (BATCH*SEQ)     // 4096
#define K2    2048            // [Ah | Al] x [Bh | Bl]; compute hh + hl + lh
#define QKVW  (EMB + 2*KVDIM) // 1536

// flash tiling: QT=128 rows per CTA, 4 warps x 32 rows, KT=64 keys
#define QT 128
#define KT 64
#define QS_STR 136
#define VS_STR 72

#define QSCALE (0.125f * 1.44269504089f)

// flash smem layout (bytes)
#define SM_Q   0
#define SM_K   34816
#define SM_VH  (SM_K + 17408)
#define SM_VL  (SM_VH + 9216)
#define SM_TOT (SM_VL + 9216)              // 70656

// gemm smem: 3 stages x 32KB
#define GEMM_SMEM (3 * 32768)

// ---------------- scratch ----------------
__device__ __nv_bfloat16 g_QKVh[ROWS * QKVW];
__device__ __nv_bfloat16 g_QKVl[ROWS * QKVW];
__device__ __nv_bfloat16 g_A   [ROWS * K2];
__device__ __nv_bfloat16 g_Bqkv[QKVW * K2];
__device__ __nv_bfloat16 g_Bo  [EMB  * K2];

// ---------------- helpers ----------------
__device__ __forceinline__ uint32_t smem_u32(const void* p) {
    uint32_t a;
    asm("{ .reg .u64 t; cvta.to.shared.u64 t, %1; cvt.u32.u64 %0, t; }" : "=r"(a) : "l"(p));
    return a;
}
__device__ __forceinline__ void ldsm_x4(uint32_t* r, uint32_t addr) {
    asm volatile("ldmatrix.sync.aligned.m8n8.x4.shared.b16 {%0,%1,%2,%3}, [%4];"
        : "=r"(r[0]), "=r"(r[1]), "=r"(r[2]), "=r"(r[3]) : "r"(addr));
}
__device__ __forceinline__ void ldsm_x2(uint32_t* r, uint32_t addr) {
    asm volatile("ldmatrix.sync.aligned.m8n8.x2.shared.b16 {%0,%1}, [%2];"
        : "=r"(r[0]), "=r"(r[1]) : "r"(addr));
}
__device__ __forceinline__ void ldsm_x2t(uint32_t* r, uint32_t addr) {
    asm volatile("ldmatrix.sync.aligned.m8n8.x2.trans.shared.b16 {%0,%1}, [%2];"
        : "=r"(r[0]), "=r"(r[1]) : "r"(addr));
}
__device__ __forceinline__ void mma16816(float* c, const uint32_t* a, const uint32_t* b) {
    asm volatile("mma.sync.aligned.m16n8k16.row.col.f32.bf16.bf16.f32 "
        "{%0,%1,%2,%3}, {%4,%5,%6,%7}, {%8,%9}, {%0,%1,%2,%3};"
        : "+f"(c[0]), "+f"(c[1]), "+f"(c[2]), "+f"(c[3])
        : "r"(a[0]), "r"(a[1]), "r"(a[2]), "r"(a[3]), "r"(b[0]), "r"(b[1]));
}
__device__ __forceinline__ float ex2f(float x) {
    float y;
    asm("ex2.approx.ftz.f32 %0, %1;" : "=f"(y) : "f"(x));
    return y;
}
__device__ __forceinline__ uint32_t pack_bf2(float a, float b) {
    __nv_bfloat162 t = __floats2bfloat162_rn(a, b);
    return *(uint32_t*)&t;
}
__device__ __forceinline__ uint32_t sw64(uint32_t off) {
    return off ^ ((off >> 3) & 0x30);
}
#define CP_ASYNC16(dst, src) \
    asm volatile("cp.async.cg.shared.global [%0], [%1], 16;" :: "r"(dst), "l"(src))
#define CP_COMMIT() asm volatile("cp.async.commit_group;" ::: "memory")
#define CP_WAIT1()  asm volatile("cp.async.wait_group 1;" ::: "memory")
#define CP_WAIT0()  asm volatile("cp.async.wait_group 0;" ::: "memory")

// ---------------- split-precision conversion kernels (R9-proven) ----------------
// X [M,1024] fp32 -> A [M, 2048] : [hi | lo]
__global__ __launch_bounds__(256) void conv_split_A(const float* __restrict__ X,
                                                    __nv_bfloat16* __restrict__ A)
{
    int idx = blockIdx.x * 256 + threadIdx.x;
    int r = idx >> 10, c = idx & 1023;
    float v = X[idx];
    __nv_bfloat16 h = __float2bfloat16(v);
    __nv_bfloat16 l = __float2bfloat16(v - __bfloat162float(h));
    size_t base = (size_t)r * K2;
    A[base + c] = h;
    A[base + 1024 + c] = l;
}
// tiled transpose: W [1024, N] -> Bt [N, 2048] = [hi | lo], both sides coalesced
__global__ __launch_bounds__(256) void conv_split_BtT(const float* __restrict__ W,
                                                      __nv_bfloat16* __restrict__ Bt, int N)
{
    __shared__ float t[32][33];
    const int n0 = blockIdx.x * 32, k0 = blockIdx.y * 32;
    const int tx = threadIdx.x, ty = threadIdx.y;   // 32 x 8
#pragma unroll
    for (int i = ty; i < 32; i += 8)
        t[i][tx] = W[(size_t)(k0 + i) * N + n0 + tx];
    __syncthreads();
#pragma unroll
    for (int i = ty; i < 32; i += 8) {
        float v = t[tx][i];
        __nv_bfloat16 h = __float2bfloat16(v);
        __nv_bfloat16 l = __float2bfloat16(v - __bfloat162float(h));
        size_t base = (size_t)(n0 + i) * K2 + k0 + tx;
        Bt[base]        = h;
        Bt[base + 1024] = l;
    }
}

// ---------------- 3-stage pipelined HMMA split GEMM ----------------
// C = Ah.Bh^T + Ah.Bl^T + Al.Bh^T. CTA tile 128x128, BK=32, 3-stage cp.async,
// ONE __syncthreads per chunk: wait -> sync -> issue(ch+2) -> compute(ch).
__global__ __launch_bounds__(256, 2) void gemm_bf16(
    const __nv_bfloat16* __restrict__ A,
    const __nv_bfloat16* __restrict__ Bt,
    float* __restrict__ C,
    __nv_bfloat16* __restrict__ Ch,
    __nv_bfloat16* __restrict__ Cl,
    int N, int mode)
{
    extern __shared__ __align__(128) char smem_g[];   // 3 stages x 32KB

    const int tid  = threadIdx.x;
    const int lane = tid & 31, wid = tid >> 5;
    const int wm = wid & 1;
    const int wn = wid >> 1;
    const int bx = blockIdx.x, by = blockIdx.y;

    const __nv_bfloat16* Ab = A  + (size_t)by * 128 * K2;
    const __nv_bfloat16* Bb = Bt + (size_t)bx * 128 * K2;

    float acc[4][4][4];
#pragma unroll
    for (int i = 0; i < 4; i++)
#pragma unroll
        for (int j = 0; j < 4; j++)
#pragma unroll
            for (int q = 0; q < 4; q++) acc[i][j][q] = 0.0f;

    const int a_r = wm * 64 + (lane & 15);
    const int a_c = (lane >> 4);
    const int b_r = wn * 32 + (lane & 7);
    const int b_c = ((lane >> 3) & 1);

    const int row_ld = tid >> 2, c16_ld = tid & 3;

    auto issue = [&](int ch, int s) {
        const int k0 = ch * 32;
        char* st = smem_g + s * 32768;
#pragma unroll
        for (int p = 0; p < 2; p++) {
            int row = row_ld + p * 64;
            uint32_t sw = sw64(row * 64 + c16_ld * 16);
            uint32_t d = smem_u32(st + sw);
            const __nv_bfloat16* ga = Ab + (size_t)row * K2 + k0 + c16_ld * 8;
            const __nv_bfloat16* gb = Bb + (size_t)row * K2 + k0 + c16_ld * 8;
            CP_ASYNC16(d,         (const char*)ga);            // Ah
            CP_ASYNC16(d + 8192,  (const char*)(ga + 1024));   // Al
            CP_ASYNC16(d + 16384, (const char*)gb);            // Bh
            CP_ASYNC16(d + 24576, (const char*)(gb + 1024));   // Bl
        }
        CP_COMMIT();
    };

    const int NCH = 1024 / 32;
    issue(0, 0);
    issue(1, 1);

    for (int ch = 0; ch < NCH; ch++) {
        // group ch must be complete; pending before this iteration's issue: {ch, ch+1}
        if (ch == NCH - 1) { CP_WAIT0(); } else { CP_WAIT1(); }
        __syncthreads();   // also guarantees all warps finished compute(ch-1)

        if (ch + 2 < NCH) issue(ch + 2, (ch + 2) % 3);   // writes stage (ch-1)%3 — safe

        const uint32_t su = smem_u32(smem_g + (ch % 3) * 32768);
#pragma unroll
        for (int ks = 0; ks < 2; ks++) {
            uint32_t bh[4][2], bl[4][2];
#pragma unroll
            for (int j = 0; j < 4; j++) {
                int row = b_r + j * 8;
                uint32_t off = sw64(row * 64 + (b_c + ks * 2) * 16);
                ldsm_x2(bh[j], su + 16384 + off);
                ldsm_x2(bl[j], su + 24576 + off);
            }
#pragma unroll
            for (int i = 0; i < 4; i++) {
                int row = a_r + i * 16;
                uint32_t off = sw64(row * 64 + (a_c + ks * 2) * 16);
                uint32_t ah[4], al[4];
                ldsm_x4(ah, su + off);
                ldsm_x4(al, su + 8192 + off);
#pragma unroll
                for (int j = 0; j < 4; j++) {
                    mma16816(acc[i][j], ah, bh[j]);
                    mma16816(acc[i][j], ah, bl[j]);
                    mma16816(acc[i][j], al, bh[j]);
                }
            }
        }
    }

    // epilogue
#pragma unroll
    for (int i = 0; i < 4; i++)
#pragma unroll
        for (int j = 0; j < 4; j++) {
            int r0  = by * 128 + wm * 64 + i * 16 + (lane >> 2);
            int col = bx * 128 + wn * 32 + j * 8 + (lane & 3) * 2;
            if (mode == 0) {
                float* p0 = C + (size_t)r0 * N + col;
                p0[0] = acc[i][j][0]; p0[1] = acc[i][j][1];
                float* p1 = p0 + (size_t)8 * N;
                p1[0] = acc[i][j][2]; p1[1] = acc[i][j][3];
            } else {
                float sc = (col < EMB) ? QSCALE : 1.0f;
                float v0 = acc[i][j][0] * sc, v1 = acc[i][j][1] * sc;
                float v2 = acc[i][j][2] * sc, v3 = acc[i][j][3] * sc;
                __nv_bfloat162 h01 = __floats2bfloat162_rn(v0, v1);
                __nv_bfloat162 h23 = __floats2bfloat162_rn(v2, v3);
                *(uint32_t*)(Ch + (size_t)r0 * N + col)       = *(uint32_t*)&h01;
                *(uint32_t*)(Ch + (size_t)(r0 + 8) * N + col) = *(uint32_t*)&h23;
                *(uint32_t*)(Cl + (size_t)r0 * N + col) =
                    pack_bf2(v0 - __bfloat162float(h01.x), v1 - __bfloat162float(h01.y));
                *(uint32_t*)(Cl + (size_t)(r0 + 8) * N + col) =
                    pack_bf2(v2 - __bfloat162float(h23.x), v3 - __bfloat162float(h23.y));
            }
        }
}

// ---------------- HMMA flash attention (R9-proven ordering: qb fastest) ----------------
// grid (SEQ/128, NH, BATCH), 128 threads = 4 warps x 32 rows, Q-hi in registers.
__global__ __launch_bounds__(128) void flash_hmma(
    const __nv_bfloat16* __restrict__ QKVh,
    const __nv_bfloat16* __restrict__ QKVl,
    __nv_bfloat16* __restrict__ Aout)
{
    extern __shared__ __align__(16) char smem[];
    __nv_bfloat16* Qs = (__nv_bfloat16*)(smem + SM_Q);
    __nv_bfloat16* Ks = (__nv_bfloat16*)(smem + SM_K);
    __nv_bfloat16* Vh = (__nv_bfloat16*)(smem + SM_VH);
    __nv_bfloat16* Vl = (__nv_bfloat16*)(smem + SM_VL);

    const int qb = blockIdx.x, h = blockIdx.y, b = blockIdx.z;
    const int g = h >> 2;
    const int tid = threadIdx.x, lane = tid & 31, wid = tid >> 5;

    const int row_ld = (tid >> 4);
    const int c4  = tid & 15;
    const int hi  = (c4 < 8);
    const __nv_bfloat16* src_ld = (hi ? QKVh : QKVl);
    const int co = (hi ? c4 : c4 - 8) * 8;
    const int kdst = (hi ? co : 64 + co);

#pragma unroll
    for (int it = 0; it < 16; it++) {
        int r = it * 8 + row_ld;
        *(uint4*)(Qs + r * QS_STR + kdst) =
            *(const uint4*)(src_ld + (size_t)(b * SEQ + qb * QT + r) * QKVW + h * HD + co);
    }
    __syncthreads();

    const uint32_t sQ = smem_u32(Qs);
    const uint32_t aQ0 = sQ + ((wid * 32 + (lane & 15)) * QS_STR + ((lane >> 4) << 3)) * 2;
    const uint32_t aQ1 = aQ0 + 16 * QS_STR * 2;
    uint32_t qh[2][4][4];
#pragma unroll
    for (int c = 0; c < 4; c++) {
        ldsm_x4(qh[0][c], aQ0 + (c * 16) * 2);
        ldsm_x4(qh[1][c], aQ1 + (c * 16) * 2);
    }

    float accO[2][8][4];
#pragma unroll
    for (int t = 0; t < 2; t++)
#pragma unroll
        for (int n = 0; n < 8; n++)
#pragma unroll
            for (int q = 0; q < 4; q++) accO[t][n][q] = 0.0f;
    float mrow[2][2], lrow[2][2];
#pragma unroll
    for (int t = 0; t < 2; t++) { mrow[t][0] = mrow[t][1] = -INFINITY; lrow[t][0] = lrow[t][1] = 0.0f; }

    const uint32_t bKh = smem_u32(Ks) + (((lane & 7)) * QS_STR + (((lane >> 3) & 1) << 3)) * 2;
    const uint32_t sVh = smem_u32(Vh), sVl = smem_u32(Vl);
    const uint32_t bVrow = (lane & 15) * VS_STR * 2;

    const int ktmax = 2 * qb + 1;
    for (int kt = 0; kt <= ktmax; kt++) {
#pragma unroll
        for (int it = 0; it < 8; it++) {
            int r = it * 8 + row_ld;
            size_t base = (size_t)(b * SEQ + kt * KT + r) * QKVW + EMB + g * HD;
            *(uint4*)(Ks + r * QS_STR + kdst) = *(const uint4*)(src_ld + base + co);
            *(uint4*)((hi ? Vh : Vl) + r * VS_STR + co) = *(const uint4*)(src_ld + base + KVDIM + co);
        }
        __syncthreads();

        float s[2][8][4];
#pragma unroll
        for (int t = 0; t < 2; t++)
#pragma unroll
            for (int n = 0; n < 8; n++)
#pragma unroll
                for (int q = 0; q < 4; q++) s[t][n][q] = 0.0f;

#pragma unroll
        for (int c = 0; c < 4; c++) {
            uint32_t ql0[4], ql1[4];
            ldsm_x4(ql0, aQ0 + (64 + c * 16) * 2);
            ldsm_x4(ql1, aQ1 + (64 + c * 16) * 2);
#pragma unroll
            for (int n = 0; n < 8; n++) {
                uint32_t kh2[2], kl2[2];
                ldsm_x2(kh2, bKh + (n * 8 * QS_STR + c * 16) * 2);
                mma16816(s[0][n], qh[0][c], kh2);
                mma16816(s[0][n], ql0, kh2);
                mma16816(s[1][n], qh[1][c], kh2);
                mma16816(s[1][n], ql1, kh2);
                ldsm_x2(kl2, bKh + (n * 8 * QS_STR + 64 + c * 16) * 2);
                mma16816(s[0][n], qh[0][c], kl2);
                mma16816(s[1][n], qh[1][c], kl2);
            }
        }

        if (kt >= 2 * qb) {
#pragma unroll
            for (int t = 0; t < 2; t++) {
                int rbase = qb * QT + wid * 32 + t * 16 + (lane >> 2);
#pragma unroll
                for (int n = 0; n < 8; n++) {
#pragma unroll
                    for (int q = 0; q < 4; q++) {
                        int colg = kt * KT + n * 8 + (lane & 3) * 2 + (q & 1);
                        int rowg = rbase + ((q >= 2) ? 8 : 0);
                        if (colg > rowg) s[t][n][q] = -1e30f;
                    }
                }
            }
        }

#pragma unroll
        for (int t = 0; t < 2; t++) {
            float mx0 = -INFINITY, mx1 = -INFINITY;
#pragma unroll
            for (int n = 0; n < 8; n++) {
                mx0 = fmaxf(mx0, fmaxf(s[t][n][0], s[t][n][1]));
                mx1 = fmaxf(mx1, fmaxf(s[t][n][2], s[t][n][3]));
            }
            mx0 = fmaxf(mx0, __shfl_xor_sync(0xffffffffu, mx0, 1));
            mx0 = fmaxf(mx0, __shfl_xor_sync(0xffffffffu, mx0, 2));
            mx1 = fmaxf(mx1, __shfl_xor_sync(0xffffffffu, mx1, 1));
            mx1 = fmaxf(mx1, __shfl_xor_sync(0xffffffffu, mx1, 2));
            float mn0 = fmaxf(mrow[t][0], mx0), mn1 = fmaxf(mrow[t][1], mx1);
            float s0 = ex2f(mrow[t][0] - mn0), s1 = ex2f(mrow[t][1] - mn1);
            lrow[t][0] *= s0; lrow[t][1] *= s1;
#pragma unroll
            for (int n = 0; n < 8; n++) {
                accO[t][n][0] *= s0; accO[t][n][1] *= s0;
                accO[t][n][2] *= s1; accO[t][n][3] *= s1;
            }
            mrow[t][0] = mn0; mrow[t][1] = mn1;

            uint32_t phx[8], phy[8], plx[8], ply[8];
#pragma unroll
            for (int n = 0; n < 8; n++) {
                float p0 = ex2f(s[t][n][0] - mn0);
                float p1 = ex2f(s[t][n][1] - mn0);
                float p2 = ex2f(s[t][n][2] - mn1);
                float p3 = ex2f(s[t][n][3] - mn1);
                lrow[t][0] += p0 + p1; lrow[t][1] += p2 + p3;
                __nv_bfloat162 h01 = __floats2bfloat162_rn(p0, p1);
                __nv_bfloat162 h23 = __floats2bfloat162_rn(p2, p3);
                phx[n] = *(uint32_t*)&h01;
                phy[n] = *(uint32_t*)&h23;
                plx[n] = pack_bf2(p0 - __bfloat162float(h01.x), p1 - __bfloat162float(h01.y));
                ply[n] = pack_bf2(p2 - __bfloat162float(h23.x), p3 - __bfloat162float(h23.y));
            }

#pragma unroll
            for (int kc = 0; kc < 4; kc++) {
                uint32_t aH[4] = {phx[2 * kc], phy[2 * kc], phx[2 * kc + 1], phy[2 * kc + 1]};
                uint32_t aL[4] = {plx[2 * kc], ply[2 * kc], plx[2 * kc + 1], ply[2 * kc + 1]};
#pragma unroll
                for (int n = 0; n < 8; n++) {
                    uint32_t bh2[2], bl2[2];
                    ldsm_x2t(bh2, sVh + (kc * 16 * VS_STR + n * 8) * 2 + bVrow);
                    ldsm_x2t(bl2, sVl + (kc * 16 * VS_STR + n * 8) * 2 + bVrow);
                    mma16816(accO[t][n], aH, bh2);
                    mma16816(accO[t][n], aL, bh2);
                    mma16816(accO[t][n], aH, bl2);
                }
            }
        }
        __syncthreads();
    }

    // ---- finalize: normalize + split store into A layout [hi|lo] ----
#pragma unroll
    for (int t = 0; t < 2; t++) {
        float l0 = lrow[t][0], l1 = lrow[t][1];
        l0 += __shfl_xor_sync(0xffffffffu, l0, 1);
        l0 += __shfl_xor_sync(0xffffffffu, l0, 2);
        l1 += __shfl_xor_sync(0xffffffffu, l1, 1);
        l1 += __shfl_xor_sync(0xffffffffu, l1, 2);
        const float inv0 = 1.0f / l0, inv1 = 1.0f / l1;

        const int r0 = qb * QT + wid * 32 + t * 16 + (lane >> 2);
#pragma unroll
        for (int n = 0; n < 8; n++) {
            int col = h * HD + n * 8 + (lane & 3) * 2;
            float v0 = accO[t][n][0] * inv0, v1 = accO[t][n][1] * inv0;
            float v2 = accO[t][n][2] * inv1, v3 = accO[t][n][3] * inv1;
            __nv_bfloat162 h01 = __floats2bfloat162_rn(v0, v1);
            __nv_bfloat162 h23 = __floats2bfloat162_rn(v2, v3);
            uint32_t lo01 = pack_bf2(v0 - __bfloat162float(h01.x), v1 - __bfloat162float(h01.y));
            uint32_t lo23 = pack_bf2(v2 - __bfloat162float(h23.x), v3 - __bfloat162float(h23.y));
            size_t ra = (size_t)(b * SEQ + r0) * K2;
            size_t rb = (size_t)(b * SEQ + r0 + 8) * K2;
            *(uint32_t*)(Aout + ra + col)        = *(uint32_t*)&h01;
            *(uint32_t*)(Aout + ra + 1024 + col) = lo01;
            *(uint32_t*)(Aout + rb + col)        = *(uint32_t*)&h23;
            *(uint32_t*)(Aout + rb + 1024 + col) = lo23;
        }
    }
}

// ---------------- launch ----------------
extern "C" void kernel_launch(void* const* d_in, const int* in_sizes, int n_in,
                              void* d_out, int out_size)
{
    const float* x  = (const float*)d_in[0];
    const float* Wq = (const float*)d_in[1];
    const float* Wk = (const float*)d_in[2];
    const float* Wv = (const float*)d_in[3];
    const float* Wo = (const float*)d_in[4];
    float* out = (float*)d_out;

    __nv_bfloat16 *QKVh, *QKVl, *A, *Bqkv, *Bo;
    cudaGetSymbolAddress((void**)&QKVh, g_QKVh);
    cudaGetSymbolAddress((void**)&QKVl, g_QKVl);
    cudaGetSymbolAddress((void**)&A, g_A);
    cudaGetSymbolAddress((void**)&Bqkv, g_Bqkv);
    cudaGetSymbolAddress((void**)&Bo, g_Bo);

    static bool attr_set = false;
    if (!attr_set) {
        cudaFuncSetAttribute(flash_hmma, cudaFuncAttributeMaxDynamicSharedMemorySize, SM_TOT);
        cudaFuncSetAttribute(gemm_bf16, cudaFuncAttributeMaxDynamicSharedMemorySize, GEMM_SMEM);
        attr_set = true;
    }

    // split-precision conversions (separate launches — R9-proven)
    conv_split_A<<<ROWS * EMB / 256, 256>>>(x, A);
    conv_split_BtT<<<dim3(EMB / 32, 32), dim3(32, 8)>>>(Wq, Bqkv, EMB);
    conv_split_BtT<<<dim3(KVDIM / 32, 32), dim3(32, 8)>>>(Wk, Bqkv + (size_t)EMB * K2, KVDIM);
    conv_split_BtT<<<dim3(KVDIM / 32, 32), dim3(32, 8)>>>(Wv, Bqkv + (size_t)(EMB + KVDIM) * K2, KVDIM);
    conv_split_BtT<<<dim3(EMB / 32, 32), dim3(32, 8)>>>(Wo, Bo, EMB);

    // fused QKV projection -> split bf16 (Q pre-scaled)
    gemm_bf16<<<dim3(QKVW / 128, ROWS / 128), 256, GEMM_SMEM>>>(
        A, Bqkv, nullptr, QKVh, QKVl, QKVW, 1);

    // flash attention -> split A layout
    flash_hmma<<<dim3(SEQ / QT, NH, BATCH), 128, SM_TOT>>>(QKVh, QKVl, A);

    // output projection -> fp32 out
    gemm_bf16<<<dim3(EMB / 128, ROWS / 128), 256, GEMM_SMEM>>>(
        A, Bo, out, nullptr, nullptr, EMB, 0);
}

// round 12
// speedup vs baseline: 1.2889x; 1.0360x over previous
#include <cuda_runtime.h>
#include <cuda_bf16.h>
#include <math.h>
#include <cstdint>

// Problem constants
#define BATCH 2
#define SEQ   2048
#define EMB   1024
#define NH    16
#define NKV   4
#define HD    64
#define KVDIM 256
#define ROWS  (BATCH*SEQ)     // 4096
#define K2    2048            // [Ah | Al] x [Bh | Bl]; compute hh + hl + lh
#define QKVW  (EMB + 2*KVDIM) // 1536

// flash tiling: QT=128 rows per CTA, 4 warps x 32 rows, KT=64 keys
#define QT 128
#define KT 64
#define QS_STR 136
#define VS_STR 72

#define QSCALE (0.125f * 1.44269504089f)

// flash smem layout (bytes)
#define SM_Q   0
#define SM_K   34816
#define SM_VH  (SM_K + 17408)
#define SM_VL  (SM_VH + 9216)
#define SM_TOT (SM_VL + 9216)              // 70656

// gemm smem: 3 stages x 32KB
#define GEMM_SMEM (3 * 32768)

// ---------------- scratch ----------------
__device__ __nv_bfloat16 g_QKVh[ROWS * QKVW];
__device__ __nv_bfloat16 g_QKVl[ROWS * QKVW];
__device__ __nv_bfloat16 g_A   [ROWS * K2];
__device__ __nv_bfloat16 g_Bqkv[QKVW * K2];
__device__ __nv_bfloat16 g_Bo  [EMB  * K2];

// ---------------- helpers ----------------
__device__ __forceinline__ uint32_t smem_u32(const void* p) {
    uint32_t a;
    asm("{ .reg .u64 t; cvta.to.shared.u64 t, %1; cvt.u32.u64 %0, t; }" : "=r"(a) : "l"(p));
    return a;
}
__device__ __forceinline__ void ldsm_x4(uint32_t* r, uint32_t addr) {
    asm volatile("ldmatrix.sync.aligned.m8n8.x4.shared.b16 {%0,%1,%2,%3}, [%4];"
        : "=r"(r[0]), "=r"(r[1]), "=r"(r[2]), "=r"(r[3]) : "r"(addr));
}
__device__ __forceinline__ void ldsm_x2(uint32_t* r, uint32_t addr) {
    asm volatile("ldmatrix.sync.aligned.m8n8.x2.shared.b16 {%0,%1}, [%2];"
        : "=r"(r[0]), "=r"(r[1]) : "r"(addr));
}
__device__ __forceinline__ void ldsm_x2t(uint32_t* r, uint32_t addr) {
    asm volatile("ldmatrix.sync.aligned.m8n8.x2.trans.shared.b16 {%0,%1}, [%2];"
        : "=r"(r[0]), "=r"(r[1]) : "r"(addr));
}
__device__ __forceinline__ void mma16816(float* c, const uint32_t* a, const uint32_t* b) {
    asm volatile("mma.sync.aligned.m16n8k16.row.col.f32.bf16.bf16.f32 "
        "{%0,%1,%2,%3}, {%4,%5,%6,%7}, {%8,%9}, {%0,%1,%2,%3};"
        : "+f"(c[0]), "+f"(c[1]), "+f"(c[2]), "+f"(c[3])
        : "r"(a[0]), "r"(a[1]), "r"(a[2]), "r"(a[3]), "r"(b[0]), "r"(b[1]));
}
__device__ __forceinline__ float ex2f(float x) {
    float y;
    asm("ex2.approx.ftz.f32 %0, %1;" : "=f"(y) : "f"(x));
    return y;
}
__device__ __forceinline__ uint32_t pack_bf2(float a, float b) {
    __nv_bfloat162 t = __floats2bfloat162_rn(a, b);
    return *(uint32_t*)&t;
}
__device__ __forceinline__ uint32_t sw64(uint32_t off) {
    return off ^ ((off >> 3) & 0x30);
}
#define CP_ASYNC16(dst, src) \
    asm volatile("cp.async.cg.shared.global [%0], [%1], 16;" :: "r"(dst), "l"(src))
#define CP_COMMIT() asm volatile("cp.async.commit_group;" ::: "memory")
#define CP_WAIT1()  asm volatile("cp.async.wait_group 1;" ::: "memory")
#define CP_WAIT0()  asm volatile("cp.async.wait_group 0;" ::: "memory")

// ---------------- split-precision conversion kernels ----------------
__global__ __launch_bounds__(256) void conv_split_A(const float* __restrict__ X,
                                                    __nv_bfloat16* __restrict__ A)
{
    int idx = blockIdx.x * 256 + threadIdx.x;
    int r = idx >> 10, c = idx & 1023;
    float v = X[idx];
    __nv_bfloat16 h = __float2bfloat16(v);
    __nv_bfloat16 l = __float2bfloat16(v - __bfloat162float(h));
    size_t base = (size_t)r * K2;
    A[base + c] = h;
    A[base + 1024 + c] = l;
}
__global__ __launch_bounds__(256) void conv_split_BtT(const float* __restrict__ W,
                                                      __nv_bfloat16* __restrict__ Bt, int N)
{
    __shared__ float t[32][33];
    const int n0 = blockIdx.x * 32, k0 = blockIdx.y * 32;
    const int tx = threadIdx.x, ty = threadIdx.y;   // 32 x 8
#pragma unroll
    for (int i = ty; i < 32; i += 8)
        t[i][tx] = W[(size_t)(k0 + i) * N + n0 + tx];
    __syncthreads();
#pragma unroll
    for (int i = ty; i < 32; i += 8) {
        float v = t[tx][i];
        __nv_bfloat16 h = __float2bfloat16(v);
        __nv_bfloat16 l = __float2bfloat16(v - __bfloat162float(h));
        size_t base = (size_t)(n0 + i) * K2 + k0 + tx;
        Bt[base]        = h;
        Bt[base + 1024] = l;
    }
}

// ---------------- 3-stage pipelined HMMA split GEMM, warp tile 64x64 ----------------
// C = Ah.Bh^T + Ah.Bl^T + Al.Bh^T. CTA tile 128x128, BK=32, 128 threads = 2x2 warps.
// Warp tile 64x64: LDS bytes/MAC = 0.0417 -> tensor-bound (was 0.0625 co-bound).
__global__ __launch_bounds__(128, 2) void gemm_bf16(
    const __nv_bfloat16* __restrict__ A,
    const __nv_bfloat16* __restrict__ Bt,
    float* __restrict__ C,
    __nv_bfloat16* __restrict__ Ch,
    __nv_bfloat16* __restrict__ Cl,
    int N, int mode)
{
    extern __shared__ __align__(128) char smem_g[];   // 3 stages x 32KB

    const int tid  = threadIdx.x;
    const int lane = tid & 31, wid = tid >> 5;
    const int wm = wid & 1;          // 2 warps over M (64 rows each)
    const int wn = wid >> 1;         // 2 warps over N (64 cols each)
    const int bx = blockIdx.x, by = blockIdx.y;

    const __nv_bfloat16* Ab = A  + (size_t)by * 128 * K2;
    const __nv_bfloat16* Bb = Bt + (size_t)bx * 128 * K2;

    float acc[4][8][4];
#pragma unroll
    for (int i = 0; i < 4; i++)
#pragma unroll
        for (int j = 0; j < 8; j++)
#pragma unroll
            for (int q = 0; q < 4; q++) acc[i][j][q] = 0.0f;

    const int a_r = wm * 64 + (lane & 15);
    const int a_c = (lane >> 4);
    const int b_r = wn * 64 + (lane & 7);
    const int b_c = ((lane >> 3) & 1);

    // cp.async mapping: 128 threads, 4 subtiles x 512 slots = 2048 slots, 16/thread
    const int row_ld = tid >> 2, c16_ld = tid & 3;    // rows 0..31 (+32 per p), 4 col-slots

    auto issue = [&](int ch, int s) {
        const int k0 = ch * 32;
        char* st = smem_g + s * 32768;
#pragma unroll
        for (int p = 0; p < 4; p++) {
            int row = row_ld + p * 32;
            uint32_t sw = sw64(row * 64 + c16_ld * 16);
            uint32_t d = smem_u32(st + sw);
            const __nv_bfloat16* ga = Ab + (size_t)row * K2 + k0 + c16_ld * 8;
            const __nv_bfloat16* gb = Bb + (size_t)row * K2 + k0 + c16_ld * 8;
            CP_ASYNC16(d,         (const char*)ga);            // Ah
            CP_ASYNC16(d + 8192,  (const char*)(ga + 1024));   // Al
            CP_ASYNC16(d + 16384, (const char*)gb);            // Bh
            CP_ASYNC16(d + 24576, (const char*)(gb + 1024));   // Bl
        }
        CP_COMMIT();
    };

    const int NCH = 1024 / 32;
    issue(0, 0);
    issue(1, 1);

    for (int ch = 0; ch < NCH; ch++) {
        if (ch == NCH - 1) { CP_WAIT0(); } else { CP_WAIT1(); }
        __syncthreads();   // also: all warps finished compute(ch-1)

        if (ch + 2 < NCH) issue(ch + 2, (ch + 2) % 3);   // writes stage (ch-1)%3 — safe

        const uint32_t su = smem_u32(smem_g + (ch % 3) * 32768);
#pragma unroll
        for (int ks = 0; ks < 2; ks++) {
            uint32_t bh[8][2], bl[8][2];
#pragma unroll
            for (int j = 0; j < 8; j++) {
                int row = b_r + j * 8;
                uint32_t off = sw64(row * 64 + (b_c + ks * 2) * 16);
                ldsm_x2(bh[j], su + 16384 + off);
                ldsm_x2(bl[j], su + 24576 + off);
            }
#pragma unroll
            for (int i = 0; i < 4; i++) {
                int row = a_r + i * 16;
                uint32_t off = sw64(row * 64 + (a_c + ks * 2) * 16);
                uint32_t ah[4], al[4];
                ldsm_x4(ah, su + off);
                ldsm_x4(al, su + 8192 + off);
#pragma unroll
                for (int j = 0; j < 8; j++) {
                    mma16816(acc[i][j], ah, bh[j]);
                    mma16816(acc[i][j], ah, bl[j]);
                    mma16816(acc[i][j], al, bh[j]);
                }
            }
        }
    }

    // epilogue
#pragma unroll
    for (int i = 0; i < 4; i++)
#pragma unroll
        for (int j = 0; j < 8; j++) {
            int r0  = by * 128 + wm * 64 + i * 16 + (lane >> 2);
            int col = bx * 128 + wn * 64 + j * 8 + (lane & 3) * 2;
            if (mode == 0) {
                float* p0 = C + (size_t)r0 * N + col;
                p0[0] = acc[i][j][0]; p0[1] = acc[i][j][1];
                float* p1 = p0 + (size_t)8 * N;
                p1[0] = acc[i][j][2]; p1[1] = acc[i][j][3];
            } else {
                float sc = (col < EMB) ? QSCALE : 1.0f;
                float v0 = acc[i][j][0] * sc, v1 = acc[i][j][1] * sc;
                float v2 = acc[i][j][2] * sc, v3 = acc[i][j][3] * sc;
                __nv_bfloat162 h01 = __floats2bfloat162_rn(v0, v1);
                __nv_bfloat162 h23 = __floats2bfloat162_rn(v2, v3);
                *(uint32_t*)(Ch + (size_t)r0 * N + col)       = *(uint32_t*)&h01;
                *(uint32_t*)(Ch + (size_t)(r0 + 8) * N + col) = *(uint32_t*)&h23;
                *(uint32_t*)(Cl + (size_t)r0 * N + col) =
                    pack_bf2(v0 - __bfloat162float(h01.x), v1 - __bfloat162float(h01.y));
                *(uint32_t*)(Cl + (size_t)(r0 + 8) * N + col) =
                    pack_bf2(v2 - __bfloat162float(h23.x), v3 - __bfloat162float(h23.y));
            }
        }
}

// ---------------- HMMA flash attention (R9-proven; unchanged) ----------------
__global__ __launch_bounds__(128) void flash_hmma(
    const __nv_bfloat16* __restrict__ QKVh,
    const __nv_bfloat16* __restrict__ QKVl,
    __nv_bfloat16* __restrict__ Aout)
{
    extern __shared__ __align__(16) char smem[];
    __nv_bfloat16* Qs = (__nv_bfloat16*)(smem + SM_Q);
    __nv_bfloat16* Ks = (__nv_bfloat16*)(smem + SM_K);
    __nv_bfloat16* Vh = (__nv_bfloat16*)(smem + SM_VH);
    __nv_bfloat16* Vl = (__nv_bfloat16*)(smem + SM_VL);

    const int qb = blockIdx.x, h = blockIdx.y, b = blockIdx.z;
    const int g = h >> 2;
    const int tid = threadIdx.x, lane = tid & 31, wid = tid >> 5;

    const int row_ld = (tid >> 4);
    const int c4  = tid & 15;
    const int hi  = (c4 < 8);
    const __nv_bfloat16* src_ld = (hi ? QKVh : QKVl);
    const int co = (hi ? c4 : c4 - 8) * 8;
    const int kdst = (hi ? co : 64 + co);

#pragma unroll
    for (int it = 0; it < 16; it++) {
        int r = it * 8 + row_ld;
        *(uint4*)(Qs + r * QS_STR + kdst) =
            *(const uint4*)(src_ld + (size_t)(b * SEQ + qb * QT + r) * QKVW + h * HD + co);
    }
    __syncthreads();

    const uint32_t sQ = smem_u32(Qs);
    const uint32_t aQ0 = sQ + ((wid * 32 + (lane & 15)) * QS_STR + ((lane >> 4) << 3)) * 2;
    const uint32_t aQ1 = aQ0 + 16 * QS_STR * 2;
    uint32_t qh[2][4][4];
#pragma unroll
    for (int c = 0; c < 4; c++) {
        ldsm_x4(qh[0][c], aQ0 + (c * 16) * 2);
        ldsm_x4(qh[1][c], aQ1 + (c * 16) * 2);
    }

    float accO[2][8][4];
#pragma unroll
    for (int t = 0; t < 2; t++)
#pragma unroll
        for (int n = 0; n < 8; n++)
#pragma unroll
            for (int q = 0; q < 4; q++) accO[t][n][q] = 0.0f;
    float mrow[2][2], lrow[2][2];
#pragma unroll
    for (int t = 0; t < 2; t++) { mrow[t][0] = mrow[t][1] = -INFINITY; lrow[t][0] = lrow[t][1] = 0.0f; }

    const uint32_t bKh = smem_u32(Ks) + (((lane & 7)) * QS_STR + (((lane >> 3) & 1) << 3)) * 2;
    const uint32_t sVh = smem_u32(Vh), sVl = smem_u32(Vl);
    const uint32_t bVrow = (lane & 15) * VS_STR * 2;

    const int ktmax = 2 * qb + 1;
    for (int kt = 0; kt <= ktmax; kt++) {
#pragma unroll
        for (int it = 0; it < 8; it++) {
            int r = it * 8 + row_ld;
            size_t base = (size_t)(b * SEQ + kt * KT + r) * QKVW + EMB + g * HD;
            *(uint4*)(Ks + r * QS_STR + kdst) = *(const uint4*)(src_ld + base + co);
            *(uint4*)((hi ? Vh : Vl) + r * VS_STR + co) = *(const uint4*)(src_ld + base + KVDIM + co);
        }
        __syncthreads();

        float s[2][8][4];
#pragma unroll
        for (int t = 0; t < 2; t++)
#pragma unroll
            for (int n = 0; n < 8; n++)
#pragma unroll
                for (int q = 0; q < 4; q++) s[t][n][q] = 0.0f;

#pragma unroll
        for (int c = 0; c < 4; c++) {
            uint32_t ql0[4], ql1[4];
            ldsm_x4(ql0, aQ0 + (64 + c * 16) * 2);
            ldsm_x4(ql1, aQ1 + (64 + c * 16) * 2);
#pragma unroll
            for (int n = 0; n < 8; n++) {
                uint32_t kh2[2], kl2[2];
                ldsm_x2(kh2, bKh + (n * 8 * QS_STR + c * 16) * 2);
                mma16816(s[0][n], qh[0][c], kh2);
                mma16816(s[0][n], ql0, kh2);
                mma16816(s[1][n], qh[1][c], kh2);
                mma16816(s[1][n], ql1, kh2);
                ldsm_x2(kl2, bKh + (n * 8 * QS_STR + 64 + c * 16) * 2);
                mma16816(s[0][n], qh[0][c], kl2);
                mma16816(s[1][n], qh[1][c], kl2);
            }
        }

        if (kt >= 2 * qb) {
#pragma unroll
            for (int t = 0; t < 2; t++) {
                int rbase = qb * QT + wid * 32 + t * 16 + (lane >> 2);
#pragma unroll
                for (int n = 0; n < 8; n++) {
#pragma unroll
                    for (int q = 0; q < 4; q++) {
                        int colg = kt * KT + n * 8 + (lane & 3) * 2 + (q & 1);
                        int rowg = rbase + ((q >= 2) ? 8 : 0);
                        if (colg > rowg) s[t][n][q] = -1e30f;
                    }
                }
            }
        }

#pragma unroll
        for (int t = 0; t < 2; t++) {
            float mx0 = -INFINITY, mx1 = -INFINITY;
#pragma unroll
            for (int n = 0; n < 8; n++) {
                mx0 = fmaxf(mx0, fmaxf(s[t][n][0], s[t][n][1]));
                mx1 = fmaxf(mx1, fmaxf(s[t][n][2], s[t][n][3]));
            }
            mx0 = fmaxf(mx0, __shfl_xor_sync(0xffffffffu, mx0, 1));
            mx0 = fmaxf(mx0, __shfl_xor_sync(0xffffffffu, mx0, 2));
            mx1 = fmaxf(mx1, __shfl_xor_sync(0xffffffffu, mx1, 1));
            mx1 = fmaxf(mx1, __shfl_xor_sync(0xffffffffu, mx1, 2));
            float mn0 = fmaxf(mrow[t][0], mx0), mn1 = fmaxf(mrow[t][1], mx1);
            float s0 = ex2f(mrow[t][0] - mn0), s1 = ex2f(mrow[t][1] - mn1);
            lrow[t][0] *= s0; lrow[t][1] *= s1;
#pragma unroll
            for (int n = 0; n < 8; n++) {
                accO[t][n][0] *= s0; accO[t][n][1] *= s0;
                accO[t][n][2] *= s1; accO[t][n][3] *= s1;
            }
            mrow[t][0] = mn0; mrow[t][1] = mn1;

            uint32_t phx[8], phy[8], plx[8], ply[8];
#pragma unroll
            for (int n = 0; n < 8; n++) {
                float p0 = ex2f(s[t][n][0] - mn0);
                float p1 = ex2f(s[t][n][1] - mn0);
                float p2 = ex2f(s[t][n][2] - mn1);
                float p3 = ex2f(s[t][n][3] - mn1);
                lrow[t][0] += p0 + p1; lrow[t][1] += p2 + p3;
                __nv_bfloat162 h01 = __floats2bfloat162_rn(p0, p1);
                __nv_bfloat162 h23 = __floats2bfloat162_rn(p2, p3);
                phx[n] = *(uint32_t*)&h01;
                phy[n] = *(uint32_t*)&h23;
                plx[n] = pack_bf2(p0 - __bfloat162float(h01.x), p1 - __bfloat162float(h01.y));
                ply[n] = pack_bf2(p2 - __bfloat162float(h23.x), p3 - __bfloat162float(h23.y));
            }

#pragma unroll
            for (int kc = 0; kc < 4; kc++) {
                uint32_t aH[4] = {phx[2 * kc], phy[2 * kc], phx[2 * kc + 1], phy[2 * kc + 1]};
                uint32_t aL[4] = {plx[2 * kc], ply[2 * kc], plx[2 * kc + 1], ply[2 * kc + 1]};
#pragma unroll
                for (int n = 0; n < 8; n++) {
                    uint32_t bh2[2], bl2[2];
                    ldsm_x2t(bh2, sVh + (kc * 16 * VS_STR + n * 8) * 2 + bVrow);
                    ldsm_x2t(bl2, sVl + (kc * 16 * VS_STR + n * 8) * 2 + bVrow);
                    mma16816(accO[t][n], aH, bh2);
                    mma16816(accO[t][n], aL, bh2);
                    mma16816(accO[t][n], aH, bl2);
                }
            }
        }
        __syncthreads();
    }

#pragma unroll
    for (int t = 0; t < 2; t++) {
        float l0 = lrow[t][0], l1 = lrow[t][1];
        l0 += __shfl_xor_sync(0xffffffffu, l0, 1);
        l0 += __shfl_xor_sync(0xffffffffu, l0, 2);
        l1 += __shfl_xor_sync(0xffffffffu, l1, 1);
        l1 += __shfl_xor_sync(0xffffffffu, l1, 2);
        const float inv0 = 1.0f / l0, inv1 = 1.0f / l1;

        const int r0 = qb * QT + wid * 32 + t * 16 + (lane >> 2);
#pragma unroll
        for (int n = 0; n < 8; n++) {
            int col = h * HD + n * 8 + (lane & 3) * 2;
            float v0 = accO[t][n][0] * inv0, v1 = accO[t][n][1] * inv0;
            float v2 = accO[t][n][2] * inv1, v3 = accO[t][n][3] * inv1;
            __nv_bfloat162 h01 = __floats2bfloat162_rn(v0, v1);
            __nv_bfloat162 h23 = __floats2bfloat162_rn(v2, v3);
            uint32_t lo01 = pack_bf2(v0 - __bfloat162float(h01.x), v1 - __bfloat162float(h01.y));
            uint32_t lo23 = pack_bf2(v2 - __bfloat162float(h23.x), v3 - __bfloat162float(h23.y));
            size_t ra = (size_t)(b * SEQ + r0) * K2;
            size_t rb = (size_t)(b * SEQ + r0 + 8) * K2;
            *(uint32_t*)(Aout + ra + col)        = *(uint32_t*)&h01;
            *(uint32_t*)(Aout + ra + 1024 + col) = lo01;
            *(uint32_t*)(Aout + rb + col)        = *(uint32_t*)&h23;
            *(uint32_t*)(Aout + rb + 1024 + col) = lo23;
        }
    }
}

// ---------------- launch ----------------
extern "C" void kernel_launch(void* const* d_in, const int* in_sizes, int n_in,
                              void* d_out, int out_size)
{
    const float* x  = (const float*)d_in[0];
    const float* Wq = (const float*)d_in[1];
    const float* Wk = (const float*)d_in[2];
    const float* Wv = (const float*)d_in[3];
    const float* Wo = (const float*)d_in[4];
    float* out = (float*)d_out;

    __nv_bfloat16 *QKVh, *QKVl, *A, *Bqkv, *Bo;
    cudaGetSymbolAddress((void**)&QKVh, g_QKVh);
    cudaGetSymbolAddress((void**)&QKVl, g_QKVl);
    cudaGetSymbolAddress((void**)&A, g_A);
    cudaGetSymbolAddress((void**)&Bqkv, g_Bqkv);
    cudaGetSymbolAddress((void**)&Bo, g_Bo);

    static bool attr_set = false;
    if (!attr_set) {
        cudaFuncSetAttribute(flash_hmma, cudaFuncAttributeMaxDynamicSharedMemorySize, SM_TOT);
        cudaFuncSetAttribute(gemm_bf16, cudaFuncAttributeMaxDynamicSharedMemorySize, GEMM_SMEM);
        attr_set = true;
    }

    // split-precision conversions
    conv_split_A<<<ROWS * EMB / 256, 256>>>(x, A);
    conv_split_BtT<<<dim3(EMB / 32, 32), dim3(32, 8)>>>(Wq, Bqkv, EMB);
    conv_split_BtT<<<dim3(KVDIM / 32, 32), dim3(32, 8)>>>(Wk, Bqkv + (size_t)EMB * K2, KVDIM);
    conv_split_BtT<<<dim3(KVDIM / 32, 32), dim3(32, 8)>>>(Wv, Bqkv + (size_t)(EMB + KVDIM) * K2, KVDIM);
    conv_split_BtT<<<dim3(EMB / 32, 32), dim3(32, 8)>>>(Wo, Bo, EMB);

    // fused QKV projection -> split bf16 (Q pre-scaled)
    gemm_bf16<<<dim3(QKVW / 128, ROWS / 128), 128, GEMM_SMEM>>>(
        A, Bqkv, nullptr, QKVh, QKVl, QKVW, 1);

    // flash attention -> split A layout
    flash_hmma<<<dim3(SEQ / QT, NH, BATCH), 128, SM_TOT>>>(QKVh, QKVl, A);

    // output projection -> fp32 out
    gemm_bf16<<<dim3(EMB / 128, ROWS / 128), 128, GEMM_SMEM>>>(
        A, Bo, out, nullptr, nullptr, EMB, 0);
}